// round 2
// baseline (speedup 1.0000x reference)
#include <cuda_runtime.h>
#include <stdint.h>

#define N_GRAPHS 1000
#define EPS 1e-5f
#define MAIN_THREADS 1024
#define MAIN_GRID 152   // GB300: 152 SMs -> 1 block/SM, caps L2 footprint at ~78MB

// Scratch: segment start index per graph (g_start[g] .. g_start[g+1])
__device__ int g_start[N_GRAPHS + 1];

// ---------------------------------------------------------------------------
// Kernel 1: find segment boundaries in the sorted int32 batch array.
// ---------------------------------------------------------------------------
__global__ void find_starts_kernel(const int* __restrict__ batch, int n) {
    int i = blockIdx.x * blockDim.x + threadIdx.x;
    if (i >= n) return;
    int b = batch[i];
    b = min(max(b, 0), N_GRAPHS - 1);          // defensive clamp
    if (i == 0) {
        for (int g = 0; g <= b; ++g) g_start[g] = 0;
    } else {
        int pb = batch[i - 1];
        pb = min(max(pb, 0), N_GRAPHS - 1);
        for (int g = pb + 1; g <= b; ++g) g_start[g] = i;
    }
    if (i == n - 1) {
        for (int g = b + 1; g <= N_GRAPHS; ++g) g_start[g] = n;
    }
}

// ---------------------------------------------------------------------------
// Kernel 2: fused GraphNorm. One block per graph (grid-stride).
// Thread mapping: lane = tid&31 -> 4 channels (float4), grp = tid>>5 -> row group.
// Pass 1: accumulate sum(w), sum(w*x), sum(w*x^2) per channel.
// Pass 2: out = A[c]*x + B[c]  with A = weight*inv_std, B = bias - mean*ms*A.
// One-pass variance: var = E_w[x^2] + mean^2 * ms * (ms - 2).
// ---------------------------------------------------------------------------
__global__ __launch_bounds__(MAIN_THREADS, 1)
void graphnorm_kernel(const float4* __restrict__ x,
                      const float* __restrict__ nw,
                      const float* __restrict__ weight,
                      const float* __restrict__ bias,
                      const float* __restrict__ msc,
                      float4* __restrict__ out) {
    __shared__ float4 s_wx[32][32];
    __shared__ float4 s_wx2[32][32];
    __shared__ float  s_w[32];
    __shared__ float4 s_A[32];
    __shared__ float4 s_B[32];

    const int lane = threadIdx.x & 31;   // channel quad: channels [lane*4, lane*4+4)
    const int grp  = threadIdx.x >> 5;   // row group: 32 groups

    for (int g = blockIdx.x; g < N_GRAPHS; g += gridDim.x) {
        const int start = g_start[g];
        const int end   = g_start[g + 1];
        if (start >= end) continue;      // uniform across block: safe

        // ---- Pass 1: weighted sums ----
        float4 wx  = make_float4(0.f, 0.f, 0.f, 0.f);
        float4 wx2 = make_float4(0.f, 0.f, 0.f, 0.f);
        float  wacc = 0.f;
        #pragma unroll 4
        for (int r = start + grp; r < end; r += 32) {
            float  w = __ldg(&nw[r]);
            float4 v = __ldg(&x[(size_t)r * 32 + lane]);
            wacc += w;
            wx.x += w * v.x;  wx.y += w * v.y;  wx.z += w * v.z;  wx.w += w * v.w;
            wx2.x += w * v.x * v.x;  wx2.y += w * v.y * v.y;
            wx2.z += w * v.z * v.z;  wx2.w += w * v.w * v.w;
        }
        s_wx[grp][lane]  = wx;
        s_wx2[grp][lane] = wx2;
        if (lane == 0) s_w[grp] = wacc;
        __syncthreads();

        // ---- Tree reduce across 32 row groups ----
        #pragma unroll
        for (int st = 16; st >= 1; st >>= 1) {
            if (grp < st) {
                float4 a = s_wx[grp][lane],  b = s_wx[grp + st][lane];
                a.x += b.x; a.y += b.y; a.z += b.z; a.w += b.w;
                s_wx[grp][lane] = a;
                float4 c = s_wx2[grp][lane], d = s_wx2[grp + st][lane];
                c.x += d.x; c.y += d.y; c.z += d.z; c.w += d.w;
                s_wx2[grp][lane] = c;
                if (lane == 0) s_w[grp] += s_w[grp + st];
            }
            __syncthreads();
        }

        // ---- Per-channel coefficients (one warp) ----
        if (grp == 0) {
            float wsum = fmaxf(s_w[0], 1e-12f);
            float inv_w = 1.0f / wsum;
            float4 m  = s_wx[0][lane];
            float4 m2 = s_wx2[0][lane];
            m.x  *= inv_w; m.y  *= inv_w; m.z  *= inv_w; m.w  *= inv_w;
            m2.x *= inv_w; m2.y *= inv_w; m2.z *= inv_w; m2.w *= inv_w;
            float4 ms = __ldg(&((const float4*)msc)[lane]);
            float4 wt = __ldg(&((const float4*)weight)[lane]);
            float4 bs = __ldg(&((const float4*)bias)[lane]);
            // var = E[x^2] - 2*ms*m^2 + ms^2*m^2 = m2 + m^2*ms*(ms-2)
            float4 A, B;
            {
                float var = m2.x + m.x * m.x * ms.x * (ms.x - 2.f);
                float inv = rsqrtf(var + EPS);
                A.x = wt.x * inv;  B.x = bs.x - m.x * ms.x * A.x;
            }
            {
                float var = m2.y + m.y * m.y * ms.y * (ms.y - 2.f);
                float inv = rsqrtf(var + EPS);
                A.y = wt.y * inv;  B.y = bs.y - m.y * ms.y * A.y;
            }
            {
                float var = m2.z + m.z * m.z * ms.z * (ms.z - 2.f);
                float inv = rsqrtf(var + EPS);
                A.z = wt.z * inv;  B.z = bs.z - m.z * ms.z * A.z;
            }
            {
                float var = m2.w + m.w * m.w * ms.w * (ms.w - 2.f);
                float inv = rsqrtf(var + EPS);
                A.w = wt.w * inv;  B.w = bs.w - m.w * ms.w * A.w;
            }
            s_A[lane] = A;
            s_B[lane] = B;
        }
        __syncthreads();

        // ---- Pass 2: normalize + write (x should be L2-resident) ----
        const float4 A = s_A[lane];
        const float4 B = s_B[lane];
        #pragma unroll 4
        for (int r = start + grp; r < end; r += 32) {
            float4 v = __ldcs(&x[(size_t)r * 32 + lane]);   // last use: evict-first
            float4 o;
            o.x = fmaf(A.x, v.x, B.x);
            o.y = fmaf(A.y, v.y, B.y);
            o.z = fmaf(A.z, v.z, B.z);
            o.w = fmaf(A.w, v.w, B.w);
            __stcs(&out[(size_t)r * 32 + lane], o);         // streaming store
        }
        __syncthreads();  // smem reuse by next graph
    }
}

// ---------------------------------------------------------------------------
// Launch
// ---------------------------------------------------------------------------
extern "C" void kernel_launch(void* const* d_in, const int* in_sizes, int n_in,
                              void* d_out, int out_size) {
    const float* x      = (const float*)d_in[0];
    const int*   batch  = (const int*)d_in[1];     // int32 (JAX x64 disabled)
    const float* nw     = (const float*)d_in[2];
    const float* weight = (const float*)d_in[3];
    const float* bias   = (const float*)d_in[4];
    const float* msc    = (const float*)d_in[5];
    float* out = (float*)d_out;

    const int n = in_sizes[1];  // number of nodes (batch length)

    find_starts_kernel<<<(n + 255) / 256, 256>>>(batch, n);
    graphnorm_kernel<<<MAIN_GRID, MAIN_THREADS>>>(
        (const float4*)x, nw, weight, bias, msc, (float4*)out);
}

// round 3
// speedup vs baseline: 1.0007x; 1.0007x over previous
#include <cuda_runtime.h>
#include <stdint.h>

#define N_GRAPHS 1000
#define EPS 1e-5f
#define MAIN_THREADS 1024
#define MAIN_GRID 152   // GB300: 152 SMs -> 1 block/SM, caps L2 footprint at ~78MB

// Scratch: segment start index per graph (g_start[g] .. g_start[g+1])
__device__ int g_start[N_GRAPHS + 1];

// ---------------------------------------------------------------------------
// Kernel 1: find segment boundaries in the sorted int32 batch array.
// ---------------------------------------------------------------------------
__global__ void find_starts_kernel(const int* __restrict__ batch, int n) {
    int i = blockIdx.x * blockDim.x + threadIdx.x;
    if (i >= n) return;
    int b = batch[i];
    b = min(max(b, 0), N_GRAPHS - 1);          // defensive clamp
    if (i == 0) {
        for (int g = 0; g <= b; ++g) g_start[g] = 0;
    } else {
        int pb = batch[i - 1];
        pb = min(max(pb, 0), N_GRAPHS - 1);
        for (int g = pb + 1; g <= b; ++g) g_start[g] = i;
    }
    if (i == n - 1) {
        for (int g = b + 1; g <= N_GRAPHS; ++g) g_start[g] = n;
    }
}

// ---------------------------------------------------------------------------
// Kernel 2: fused GraphNorm. One block per graph (grid-stride).
// Thread mapping: lane = tid&31 -> 4 channels (float4), grp = tid>>5 -> row group.
// Pass 1: accumulate sum(w), sum(w*x), sum(w*x^2) per channel.
// Pass 2: out = A[c]*x + B[c]  with A = weight*inv_std, B = bias - mean*ms*A.
// One-pass variance: var = E_w[x^2] + mean^2 * ms * (ms - 2).
// ---------------------------------------------------------------------------
__global__ __launch_bounds__(MAIN_THREADS, 1)
void graphnorm_kernel(const float4* __restrict__ x,
                      const float* __restrict__ nw,
                      const float* __restrict__ weight,
                      const float* __restrict__ bias,
                      const float* __restrict__ msc,
                      float4* __restrict__ out) {
    __shared__ float4 s_wx[32][32];
    __shared__ float4 s_wx2[32][32];
    __shared__ float  s_w[32];
    __shared__ float4 s_A[32];
    __shared__ float4 s_B[32];

    const int lane = threadIdx.x & 31;   // channel quad: channels [lane*4, lane*4+4)
    const int grp  = threadIdx.x >> 5;   // row group: 32 groups

    for (int g = blockIdx.x; g < N_GRAPHS; g += gridDim.x) {
        const int start = g_start[g];
        const int end   = g_start[g + 1];
        if (start >= end) continue;      // uniform across block: safe

        // ---- Pass 1: weighted sums ----
        float4 wx  = make_float4(0.f, 0.f, 0.f, 0.f);
        float4 wx2 = make_float4(0.f, 0.f, 0.f, 0.f);
        float  wacc = 0.f;
        #pragma unroll 4
        for (int r = start + grp; r < end; r += 32) {
            float  w = __ldg(&nw[r]);
            float4 v = __ldg(&x[(size_t)r * 32 + lane]);
            wacc += w;
            wx.x += w * v.x;  wx.y += w * v.y;  wx.z += w * v.z;  wx.w += w * v.w;
            wx2.x += w * v.x * v.x;  wx2.y += w * v.y * v.y;
            wx2.z += w * v.z * v.z;  wx2.w += w * v.w * v.w;
        }
        s_wx[grp][lane]  = wx;
        s_wx2[grp][lane] = wx2;
        if (lane == 0) s_w[grp] = wacc;
        __syncthreads();

        // ---- Tree reduce across 32 row groups ----
        #pragma unroll
        for (int st = 16; st >= 1; st >>= 1) {
            if (grp < st) {
                float4 a = s_wx[grp][lane],  b = s_wx[grp + st][lane];
                a.x += b.x; a.y += b.y; a.z += b.z; a.w += b.w;
                s_wx[grp][lane] = a;
                float4 c = s_wx2[grp][lane], d = s_wx2[grp + st][lane];
                c.x += d.x; c.y += d.y; c.z += d.z; c.w += d.w;
                s_wx2[grp][lane] = c;
                if (lane == 0) s_w[grp] += s_w[grp + st];
            }
            __syncthreads();
        }

        // ---- Per-channel coefficients (one warp) ----
        if (grp == 0) {
            float wsum = fmaxf(s_w[0], 1e-12f);
            float inv_w = 1.0f / wsum;
            float4 m  = s_wx[0][lane];
            float4 m2 = s_wx2[0][lane];
            m.x  *= inv_w; m.y  *= inv_w; m.z  *= inv_w; m.w  *= inv_w;
            m2.x *= inv_w; m2.y *= inv_w; m2.z *= inv_w; m2.w *= inv_w;
            float4 ms = __ldg(&((const float4*)msc)[lane]);
            float4 wt = __ldg(&((const float4*)weight)[lane]);
            float4 bs = __ldg(&((const float4*)bias)[lane]);
            // var = E[x^2] - 2*ms*m^2 + ms^2*m^2 = m2 + m^2*ms*(ms-2)
            float4 A, B;
            {
                float var = m2.x + m.x * m.x * ms.x * (ms.x - 2.f);
                float inv = rsqrtf(var + EPS);
                A.x = wt.x * inv;  B.x = bs.x - m.x * ms.x * A.x;
            }
            {
                float var = m2.y + m.y * m.y * ms.y * (ms.y - 2.f);
                float inv = rsqrtf(var + EPS);
                A.y = wt.y * inv;  B.y = bs.y - m.y * ms.y * A.y;
            }
            {
                float var = m2.z + m.z * m.z * ms.z * (ms.z - 2.f);
                float inv = rsqrtf(var + EPS);
                A.z = wt.z * inv;  B.z = bs.z - m.z * ms.z * A.z;
            }
            {
                float var = m2.w + m.w * m.w * ms.w * (ms.w - 2.f);
                float inv = rsqrtf(var + EPS);
                A.w = wt.w * inv;  B.w = bs.w - m.w * ms.w * A.w;
            }
            s_A[lane] = A;
            s_B[lane] = B;
        }
        __syncthreads();

        // ---- Pass 2: normalize + write (x should be L2-resident) ----
        const float4 A = s_A[lane];
        const float4 B = s_B[lane];
        #pragma unroll 4
        for (int r = start + grp; r < end; r += 32) {
            float4 v = __ldcs(&x[(size_t)r * 32 + lane]);   // last use: evict-first
            float4 o;
            o.x = fmaf(A.x, v.x, B.x);
            o.y = fmaf(A.y, v.y, B.y);
            o.z = fmaf(A.z, v.z, B.z);
            o.w = fmaf(A.w, v.w, B.w);
            __stcs(&out[(size_t)r * 32 + lane], o);         // streaming store
        }
        __syncthreads();  // smem reuse by next graph
    }
}

// ---------------------------------------------------------------------------
// Launch
// ---------------------------------------------------------------------------
extern "C" void kernel_launch(void* const* d_in, const int* in_sizes, int n_in,
                              void* d_out, int out_size) {
    const float* x      = (const float*)d_in[0];
    const int*   batch  = (const int*)d_in[1];     // int32 (JAX x64 disabled)
    const float* nw     = (const float*)d_in[2];
    const float* weight = (const float*)d_in[3];
    const float* bias   = (const float*)d_in[4];
    const float* msc    = (const float*)d_in[5];
    float* out = (float*)d_out;

    const int n = in_sizes[1];  // number of nodes (batch length)

    find_starts_kernel<<<(n + 255) / 256, 256>>>(batch, n);
    graphnorm_kernel<<<MAIN_GRID, MAIN_THREADS>>>(
        (const float4*)x, nw, weight, bias, msc, (float4*)out);
}